// round 5
// baseline (speedup 1.0000x reference)
#include <cuda_runtime.h>
#include <cuda_bf16.h>
#include <math.h>

// Problem constants (fixed by setup_inputs)
#define NN      65536
#define BB      512
#define NPG     128
#define EE      262144
#define EPG     512
#define HH      256
#define FIN     128
#define BN_EPS  1e-5f

// ---------------- scratch (device globals; no cudaMalloc allowed) ----------
__device__ float d_z[NN * HH];
__device__ float d_t[NN * HH];
__device__ float d_h[NN * HH];
__device__ float d_a[NN * 2];
__device__ float d_stats[2 * HH];
__device__ float d_pen[BB];
// bf16 hi/lo split weights, [K][N] layout (same as source fp32)
// order: w0_1 (128x256), then w0_2, wl1_0, wl2_0, wl1_1, wl2_1, c1w (256x256)
#define WSPLIT_TOTAL (256 * (128 + 6 * 256))
__device__ __nv_bfloat16 d_wth[WSPLIT_TOTAL];
__device__ __nv_bfloat16 d_wtl[WSPLIT_TOTAL];

// ---------------- MMA helpers ----------------------------------------------
__device__ __forceinline__ unsigned smem_u32(const void* p) {
    return (unsigned)__cvta_generic_to_shared(p);
}
__device__ __forceinline__ void ldsm_x4(unsigned addr, unsigned& r0, unsigned& r1,
                                        unsigned& r2, unsigned& r3) {
    asm volatile("ldmatrix.sync.aligned.m8n8.x4.shared.b16 {%0,%1,%2,%3}, [%4];"
                 : "=r"(r0), "=r"(r1), "=r"(r2), "=r"(r3) : "r"(addr));
}
__device__ __forceinline__ void ldsm_x4t(unsigned addr, unsigned& r0, unsigned& r1,
                                         unsigned& r2, unsigned& r3) {
    asm volatile("ldmatrix.sync.aligned.m8n8.x4.trans.shared.b16 {%0,%1,%2,%3}, [%4];"
                 : "=r"(r0), "=r"(r1), "=r"(r2), "=r"(r3) : "r"(addr));
}
__device__ __forceinline__ void mma_bf16(float* d, const unsigned* a,
                                         unsigned b0, unsigned b1) {
    asm volatile("mma.sync.aligned.m16n8k16.row.col.f32.bf16.bf16.f32 "
                 "{%0,%1,%2,%3}, {%4,%5,%6,%7}, {%8,%9}, {%0,%1,%2,%3};"
                 : "+f"(d[0]), "+f"(d[1]), "+f"(d[2]), "+f"(d[3])
                 : "r"(a[0]), "r"(a[1]), "r"(a[2]), "r"(a[3]), "r"(b0), "r"(b1));
}
__device__ __forceinline__ void split_bf16(float v, __nv_bfloat16& h, __nv_bfloat16& l) {
    h = __float2bfloat16(v);
    l = __float2bfloat16(v - __bfloat162float(h));
}

// ---------------- per-graph aggregation ------------------------------------
template <int F>
__global__ void agg_kernel(const float* __restrict__ hin,
                           const int* __restrict__ src,
                           const int* __restrict__ dst,
                           float* __restrict__ zout) {
    extern __shared__ float sagg[];
    const int g = blockIdx.x;
    const int t = threadIdx.x;
    for (int i = t; i < NPG * F; i += F) sagg[i] = 0.f;
    __syncthreads();
    const int ebase = g * EPG;
    const int nbase = g * NPG;
    #pragma unroll 4
    for (int e = 0; e < EPG; ++e) {
        int s  = src[ebase + e];
        int dl = dst[ebase + e] - nbase;
        sagg[dl * F + t] += hin[(size_t)s * F + t];
    }
    __syncthreads();
    const size_t gb = (size_t)g * NPG * F;
    for (int i = t; i < NPG * F; i += F)
        zout[gb + i] = sagg[i] + hin[gb + i];
}

// ---------------- weight prep: fp32 [K][256] -> bf16 hi/lo planes ----------
__global__ void wsplit_kernel(const float* __restrict__ W,
                              __nv_bfloat16* __restrict__ oh,
                              __nv_bfloat16* __restrict__ ol, int total) {
    int id = blockIdx.x * 256 + threadIdx.x;
    if (id >= total) return;
    __nv_bfloat16 h, l;
    split_bf16(W[id], h, l);
    oh[id] = h; ol[id] = l;
}

// ---------------- bf16x3 HMMA GEMM, double-buffered, pre-split W -----------
// Block tile 128x128, BK=32, 256 threads (8 warps 4x2), warp tile 32x64.
#define LDA 40
#define LDW 136
#define GEMM_SMEM ((4 * 128 * LDA + 4 * 32 * LDW) * 2)

__global__ __launch_bounds__(256)
void gemm_hmma(const float* __restrict__ A,
               const __nv_bfloat16* __restrict__ Wth,
               const __nv_bfloat16* __restrict__ Wtl,
               const float* __restrict__ bias, float* __restrict__ C,
               int K, int act) {
    extern __shared__ __nv_bfloat16 sm[];
    __nv_bfloat16* Ah = sm;                       // [2][128][LDA]
    __nv_bfloat16* Al = sm + 2 * 128 * LDA;       // [2][128][LDA]
    __nv_bfloat16* Bh = sm + 4 * 128 * LDA;       // [2][32][LDW]
    __nv_bfloat16* Bl = Bh + 2 * 32 * LDW;        // [2][32][LDW]

    const int tid = threadIdx.x;
    const int lane = tid & 31;
    const int wid = tid >> 5;
    const int warp_m = wid & 3;
    const int warp_n = wid >> 2;
    const int rowBase = blockIdx.y * 128;
    const int colBase = blockIdx.x * 128;
    const int Ncol = HH;

    float acc[2][8][4] = {};

    const int lg = lane >> 3, lj = lane & 7;
    const int a_row_off = (lg & 1) * 8 + lj;
    const int a_col_off = (lg >> 1) * 8;
    const int b_k_off = (lg & 1) * 8 + lj;
    const int b_n_off = (lg >> 1) * 8;

    // staging registers
    float4 a_reg[4];
    uint4 bh_reg, bl_reg;
    // A fill indexing: idx = tid + i*256; row = idx>>3; c = (idx&7)*4
    // B fill indexing: idx = tid; row = idx>>4... only 512 uint4 per plane ->
    //   2 per thread; use i in {0,1}: idx = tid + i*256
    uint4 bh_reg2, bl_reg2;

    const int niter = K >> 5;

    // ---- load tile 'it' into registers ----
    #define LOAD_TILE(it) do {                                                \
        const int k0 = (it) * 32;                                             \
        _Pragma("unroll")                                                     \
        for (int i = 0; i < 4; ++i) {                                         \
            int idx = tid + i * 256;                                          \
            int row = idx >> 3;                                               \
            int c = (idx & 7) * 4;                                            \
            a_reg[i] = *reinterpret_cast<const float4*>(                      \
                &A[(size_t)(rowBase + row) * K + k0 + c]);                    \
        }                                                                     \
        {                                                                     \
            int idx = tid;                                                    \
            int row = idx >> 4;                                               \
            int c8 = (idx & 15) * 8;                                          \
            size_t go = (size_t)(k0 + row) * Ncol + colBase + c8;             \
            bh_reg = *reinterpret_cast<const uint4*>(&Wth[go]);               \
            bl_reg = *reinterpret_cast<const uint4*>(&Wtl[go]);               \
            idx = tid + 256;                                                  \
            row = idx >> 4;                                                   \
            c8 = (idx & 15) * 8;                                              \
            go = (size_t)(k0 + row) * Ncol + colBase + c8;                    \
            bh_reg2 = *reinterpret_cast<const uint4*>(&Wth[go]);              \
            bl_reg2 = *reinterpret_cast<const uint4*>(&Wtl[go]);              \
        }                                                                     \
    } while (0)

    // ---- store staged registers into smem buffer 'buf' ----
    #define STORE_TILE(buf) do {                                              \
        __nv_bfloat16* ah = Ah + (buf) * 128 * LDA;                           \
        __nv_bfloat16* al = Al + (buf) * 128 * LDA;                           \
        __nv_bfloat16* bh = Bh + (buf) * 32 * LDW;                            \
        __nv_bfloat16* bl = Bl + (buf) * 32 * LDW;                            \
        _Pragma("unroll")                                                     \
        for (int i = 0; i < 4; ++i) {                                         \
            int idx = tid + i * 256;                                          \
            int row = idx >> 3;                                               \
            int c = (idx & 7) * 4;                                            \
            float vv[4] = {a_reg[i].x, a_reg[i].y, a_reg[i].z, a_reg[i].w};   \
            unsigned hp[2], lp[2];                                            \
            _Pragma("unroll")                                                 \
            for (int q = 0; q < 2; ++q) {                                     \
                __nv_bfloat16 h0, l0, h1, l1;                                 \
                split_bf16(vv[2 * q], h0, l0);                                \
                split_bf16(vv[2 * q + 1], h1, l1);                            \
                hp[q] = ((unsigned)*(unsigned short*)&h1 << 16) |             \
                        *(unsigned short*)&h0;                                \
                lp[q] = ((unsigned)*(unsigned short*)&l1 << 16) |             \
                        *(unsigned short*)&l0;                                \
            }                                                                 \
            *reinterpret_cast<uint2*>(&ah[row * LDA + c]) =                   \
                make_uint2(hp[0], hp[1]);                                     \
            *reinterpret_cast<uint2*>(&al[row * LDA + c]) =                   \
                make_uint2(lp[0], lp[1]);                                     \
        }                                                                     \
        {                                                                     \
            int idx = tid;                                                    \
            int row = idx >> 4;                                               \
            int c8 = (idx & 15) * 8;                                          \
            *reinterpret_cast<uint4*>(&bh[row * LDW + c8]) = bh_reg;          \
            *reinterpret_cast<uint4*>(&bl[row * LDW + c8]) = bl_reg;          \
            idx = tid + 256;                                                  \
            row = idx >> 4;                                                   \
            c8 = (idx & 15) * 8;                                              \
            *reinterpret_cast<uint4*>(&bh[row * LDW + c8]) = bh_reg2;         \
            *reinterpret_cast<uint4*>(&bl[row * LDW + c8]) = bl_reg2;         \
        }                                                                     \
    } while (0)

    LOAD_TILE(0);
    STORE_TILE(0);
    __syncthreads();

    for (int it = 0; it < niter; ++it) {
        const int buf = it & 1;
        if (it + 1 < niter) LOAD_TILE(it + 1);

        const __nv_bfloat16* ah = Ah + buf * 128 * LDA;
        const __nv_bfloat16* al = Al + buf * 128 * LDA;
        const __nv_bfloat16* bh = Bh + buf * 32 * LDW;
        const __nv_bfloat16* bl = Bl + buf * 32 * LDW;

        #pragma unroll
        for (int ks = 0; ks < 2; ++ks) {
            const int kb = ks * 16;
            unsigned afr[2][2][4];
            #pragma unroll
            for (int mt = 0; mt < 2; ++mt) {
                int row = warp_m * 32 + mt * 16 + a_row_off;
                int col = kb + a_col_off;
                ldsm_x4(smem_u32(&ah[row * LDA + col]),
                        afr[0][mt][0], afr[0][mt][1], afr[0][mt][2], afr[0][mt][3]);
                ldsm_x4(smem_u32(&al[row * LDA + col]),
                        afr[1][mt][0], afr[1][mt][1], afr[1][mt][2], afr[1][mt][3]);
            }
            unsigned bfr[4][4];
            #pragma unroll
            for (int p = 0; p < 4; ++p) {
                int kk = kb + b_k_off;
                int nn = warp_n * 64 + p * 16 + b_n_off;
                ldsm_x4t(smem_u32(&bh[kk * LDW + nn]),
                         bfr[p][0], bfr[p][1], bfr[p][2], bfr[p][3]);
            }
            #pragma unroll
            for (int s = 0; s < 2; ++s)
                #pragma unroll
                for (int mt = 0; mt < 2; ++mt)
                    #pragma unroll
                    for (int p = 0; p < 4; ++p) {
                        mma_bf16(acc[mt][2 * p],     afr[s][mt], bfr[p][0], bfr[p][1]);
                        mma_bf16(acc[mt][2 * p + 1], afr[s][mt], bfr[p][2], bfr[p][3]);
                    }
            #pragma unroll
            for (int p = 0; p < 4; ++p) {
                int kk = kb + b_k_off;
                int nn = warp_n * 64 + p * 16 + b_n_off;
                ldsm_x4t(smem_u32(&bl[kk * LDW + nn]),
                         bfr[p][0], bfr[p][1], bfr[p][2], bfr[p][3]);
            }
            #pragma unroll
            for (int mt = 0; mt < 2; ++mt)
                #pragma unroll
                for (int p = 0; p < 4; ++p) {
                    mma_bf16(acc[mt][2 * p],     afr[0][mt], bfr[p][0], bfr[p][1]);
                    mma_bf16(acc[mt][2 * p + 1], afr[0][mt], bfr[p][2], bfr[p][3]);
                }
        }

        if (it + 1 < niter) STORE_TILE((it + 1) & 1);
        __syncthreads();
    }

    // ---- epilogue ----
    const int g = lane >> 2, tq = lane & 3;
    #pragma unroll
    for (int mt = 0; mt < 2; ++mt) {
        #pragma unroll
        for (int nt = 0; nt < 8; ++nt) {
            int row0 = rowBase + warp_m * 32 + mt * 16 + g;
            int col = colBase + warp_n * 64 + nt * 8 + 2 * tq;
            float b0 = bias[col], b1 = bias[col + 1];
            float v[4] = {acc[mt][nt][0] + b0, acc[mt][nt][1] + b1,
                          acc[mt][nt][2] + b0, acc[mt][nt][3] + b1};
            if (act == 1) {
                #pragma unroll
                for (int q = 0; q < 4; ++q) v[q] = fmaxf(v[q], 0.f);
            } else if (act == 2) {
                #pragma unroll
                for (int q = 0; q < 4; ++q) v[q] = tanhf(v[q]);
            }
            *reinterpret_cast<float2*>(&C[(size_t)row0 * Ncol + col]) =
                make_float2(v[0], v[1]);
            *reinterpret_cast<float2*>(&C[(size_t)(row0 + 8) * Ncol + col]) =
                make_float2(v[2], v[3]);
        }
    }
    #undef LOAD_TILE
    #undef STORE_TILE
}

// ---------------- BatchNorm --------------------------------------------------
__global__ void bn_zero_kernel() {
    if (threadIdx.x < 2 * HH) d_stats[threadIdx.x] = 0.f;
}
__global__ void bn_stats_kernel(const float* __restrict__ Z) {
    const int t = threadIdx.x;
    const int r0 = blockIdx.x * 256;
    float s = 0.f, s2 = 0.f;
    for (int r = 0; r < 256; ++r) {
        float v = Z[(size_t)(r0 + r) * HH + t];
        s += v; s2 += v * v;
    }
    atomicAdd(&d_stats[t], s);
    atomicAdd(&d_stats[HH + t], s2);
}
__global__ void bn_apply_kernel(const float* __restrict__ Z,
                                const float* __restrict__ gamma,
                                const float* __restrict__ beta,
                                float* __restrict__ Hout) {
    const int idx = blockIdx.x * blockDim.x + threadIdx.x;
    const int f = idx & (HH - 1);
    const float mu  = d_stats[f] * (1.f / NN);
    const float var = d_stats[HH + f] * (1.f / NN) - mu * mu;
    const float inv = rsqrtf(var + BN_EPS);
    Hout[idx] = (Z[idx] - mu) * inv * gamma[f] + beta[f];
}

// ---------------- assignment softmax ---------------------------------------
__global__ void assign_kernel(const float* __restrict__ T,
                              const float* __restrict__ c2w,
                              const float* __restrict__ c2b,
                              float* __restrict__ Aout) {
    const int lane = threadIdx.x & 31;
    const int row = blockIdx.x * 8 + (threadIdx.x >> 5);
    float s0 = 0.f, s1 = 0.f;
    #pragma unroll
    for (int k = lane; k < HH; k += 32) {
        float tv = T[(size_t)row * HH + k];
        s0 += tv * c2w[k * 2 + 0];
        s1 += tv * c2w[k * 2 + 1];
    }
    #pragma unroll
    for (int o = 16; o > 0; o >>= 1) {
        s0 += __shfl_xor_sync(0xffffffffu, s0, o);
        s1 += __shfl_xor_sync(0xffffffffu, s1, o);
    }
    if (lane == 0) {
        s0 += c2b[0]; s1 += c2b[1];
        float m = fmaxf(s0, s1);
        float e0 = expf(s0 - m), e1 = expf(s1 - m);
        float inv = 1.f / (e0 + e1);
        Aout[row * 2 + 0] = e0 * inv;
        Aout[row * 2 + 1] = e1 * inv;
    }
}

// ---------------- pooling ----------------------------------------------------
__global__ void pool_kernel(const float* __restrict__ Hh,
                            const float* __restrict__ Aa,
                            float* __restrict__ sub_out,
                            float* __restrict__ graph_out) {
    __shared__ float sa0[NPG];
    const int g = blockIdx.x, t = threadIdx.x;
    if (t < NPG) sa0[t] = Aa[(g * NPG + t) * 2];
    __syncthreads();
    float sh = 0.f, ss = 0.f;
    const size_t base = (size_t)g * NPG * HH;
    for (int r = 0; r < NPG; ++r) {
        float hv = Hh[base + r * HH + t];
        sh += hv;
        ss += sa0[r] * hv;
    }
    sub_out[g * HH + t] = ss;
    graph_out[g * HH + t] = sh * (1.f / NPG);
}

// ---------------- pooled adjacency diag penalty -----------------------------
__global__ void adj_kernel(const float* __restrict__ Aa,
                           const int* __restrict__ src,
                           const int* __restrict__ dst) {
    const int g = blockIdx.x, t = threadIdx.x;
    float m00 = 0.f, m01 = 0.f, m10 = 0.f, m11 = 0.f;
    for (int e = t; e < EPG; e += 128) {
        int se = src[g * EPG + e], de = dst[g * EPG + e];
        float a0 = Aa[se * 2], a1 = Aa[se * 2 + 1];
        float b0 = Aa[de * 2], b1 = Aa[de * 2 + 1];
        m00 += a0 * b0; m01 += a0 * b1;
        m10 += a1 * b0; m11 += a1 * b1;
    }
    __shared__ float red[4][128];
    red[0][t] = m00; red[1][t] = m01; red[2][t] = m10; red[3][t] = m11;
    __syncthreads();
    for (int s = 64; s > 0; s >>= 1) {
        if (t < s) {
            red[0][t] += red[0][t + s]; red[1][t] += red[1][t + s];
            red[2][t] += red[2][t + s]; red[3][t] += red[3][t + s];
        }
        __syncthreads();
    }
    if (t == 0) {
        float r0 = fmaxf(fabsf(red[0][0]) + fabsf(red[1][0]), 1e-12f);
        float r1 = fmaxf(fabsf(red[2][0]) + fabsf(red[3][0]), 1e-12f);
        float e0 = red[0][0] / r0 - 1.f;
        float e1 = red[3][0] / r1 - 1.f;
        d_pen[g] = 0.5f * (e0 * e0 + e1 * e1);
    }
}

__global__ void pen_reduce_kernel(float* __restrict__ outp) {
    __shared__ float s[BB];
    s[threadIdx.x] = d_pen[threadIdx.x];
    __syncthreads();
    for (int st = BB / 2; st > 0; st >>= 1) {
        if (threadIdx.x < st) s[threadIdx.x] += s[threadIdx.x + st];
        __syncthreads();
    }
    if (threadIdx.x == 0) outp[0] = s[0] * (1.f / BB);
}

// ---------------- classifier head -------------------------------------------
__global__ void head_kernel(const float* __restrict__ sub,
                            const float* __restrict__ l1w,
                            const float* __restrict__ l1b,
                            const float* __restrict__ l2w,
                            const float* __restrict__ l2b,
                            float* __restrict__ outp) {
    __shared__ float ssub[HH];
    __shared__ float red0[HH], red1[HH];
    const int r = blockIdx.x, t = threadIdx.x;
    ssub[t] = sub[r * HH + t];
    __syncthreads();
    float acc = l1b[t];
    #pragma unroll 8
    for (int k = 0; k < HH; ++k) acc += ssub[k] * l1w[k * HH + t];
    float zc = fmaxf(acc, 0.f);
    red0[t] = zc * l2w[t * 2 + 0];
    red1[t] = zc * l2w[t * 2 + 1];
    __syncthreads();
    for (int s = 128; s > 0; s >>= 1) {
        if (t < s) { red0[t] += red0[t + s]; red1[t] += red1[t + s]; }
        __syncthreads();
    }
    if (t == 0) {
        float s0 = red0[0] + l2b[0], s1 = red1[0] + l2b[1];
        float m = fmaxf(s0, s1);
        float lse = m + logf(expf(s0 - m) + expf(s1 - m));
        outp[r * 2 + 0] = s0 - lse;
        outp[r * 2 + 1] = s1 - lse;
    }
}

// ---------------- launch ------------------------------------------------------
extern "C" void kernel_launch(void* const* d_in, const int* in_sizes, int n_in,
                              void* d_out, int out_size) {
    const float* x    = (const float*)d_in[0];
    const int*   ei   = (const int*)d_in[1];
    const int*   src  = ei;
    const int*   dst  = ei + EE;
    const float* w0_1 = (const float*)d_in[3];
    const float* b0_1 = (const float*)d_in[4];
    const float* w0_2 = (const float*)d_in[5];
    const float* b0_2 = (const float*)d_in[6];
    const float* g0   = (const float*)d_in[7];
    const float* be0  = (const float*)d_in[8];
    const float* wl1  = (const float*)d_in[9];
    const float* bl1  = (const float*)d_in[10];
    const float* wl2  = (const float*)d_in[11];
    const float* bl2  = (const float*)d_in[12];
    const float* gl   = (const float*)d_in[13];
    const float* bel  = (const float*)d_in[14];
    const float* c1w  = (const float*)d_in[15];
    const float* c1b  = (const float*)d_in[16];
    const float* c2w  = (const float*)d_in[17];
    const float* c2b  = (const float*)d_in[18];
    const float* l1w  = (const float*)d_in[19];
    const float* l1b  = (const float*)d_in[20];
    const float* l2w  = (const float*)d_in[21];
    const float* l2b  = (const float*)d_in[22];

    float* out        = (float*)d_out;
    float* out_logits = out;
    float* out_sub    = out + BB * 2;
    float* out_graph  = out + BB * 2 + BB * HH;
    float* out_pen    = out + BB * 2 + 2 * BB * HH;

    float *zb, *tb, *hb, *ab;
    cudaGetSymbolAddress((void**)&zb, d_z);
    cudaGetSymbolAddress((void**)&tb, d_t);
    cudaGetSymbolAddress((void**)&hb, d_h);
    cudaGetSymbolAddress((void**)&ab, d_a);
    __nv_bfloat16 *wth, *wtl;
    cudaGetSymbolAddress((void**)&wth, d_wth);
    cudaGetSymbolAddress((void**)&wtl, d_wtl);

    cudaFuncSetAttribute(agg_kernel<FIN>, cudaFuncAttributeMaxDynamicSharedMemorySize,
                         NPG * FIN * 4);
    cudaFuncSetAttribute(agg_kernel<HH>, cudaFuncAttributeMaxDynamicSharedMemorySize,
                         NPG * HH * 4);
    cudaFuncSetAttribute(gemm_hmma, cudaFuncAttributeMaxDynamicSharedMemorySize,
                         GEMM_SMEM);

    // weight split offsets (elements), [K][N] layout
    const int O_W01 = 0;                       // 128*256
    const int O_W02 = 32768;
    const int O_L1A = 98304;
    const int O_L2A = 163840;
    const int O_L1B = 229376;
    const int O_L2B = 294912;
    const int O_C1  = 360448;

    wsplit_kernel<<<128, 256>>>(w0_1, wth + O_W01, wtl + O_W01, 128 * 256);
    wsplit_kernel<<<256, 256>>>(w0_2, wth + O_W02, wtl + O_W02, 256 * 256);
    wsplit_kernel<<<256, 256>>>(wl1,           wth + O_L1A, wtl + O_L1A, 256 * 256);
    wsplit_kernel<<<256, 256>>>(wl2,           wth + O_L2A, wtl + O_L2A, 256 * 256);
    wsplit_kernel<<<256, 256>>>(wl1 + HH * HH, wth + O_L1B, wtl + O_L1B, 256 * 256);
    wsplit_kernel<<<256, 256>>>(wl2 + HH * HH, wth + O_L2B, wtl + O_L2B, 256 * 256);
    wsplit_kernel<<<256, 256>>>(c1w,           wth + O_C1,  wtl + O_C1,  256 * 256);

    const dim3 gemm_grid(HH / 128, NN / 128);

    // ---- GIN layer 0 (F_IN -> H -> H) ----
    agg_kernel<FIN><<<BB, FIN, NPG * FIN * 4>>>(x, src, dst, zb);
    gemm_hmma<<<gemm_grid, 256, GEMM_SMEM>>>(zb, wth + O_W01, wtl + O_W01, b0_1, tb, FIN, 1);
    gemm_hmma<<<gemm_grid, 256, GEMM_SMEM>>>(tb, wth + O_W02, wtl + O_W02, b0_2, zb, HH, 1);
    bn_zero_kernel<<<1, 512>>>();
    bn_stats_kernel<<<NN / 256, 256>>>(zb);
    bn_apply_kernel<<<(NN * HH) / 256, 256>>>(zb, g0, be0, hb);

    // ---- GIN layers 1..2 ----
    const int offs1[2] = {O_L1A, O_L1B};
    const int offs2[2] = {O_L2A, O_L2B};
    for (int i = 0; i < 2; ++i) {
        agg_kernel<HH><<<BB, HH, NPG * HH * 4>>>(hb, src, dst, zb);
        gemm_hmma<<<gemm_grid, 256, GEMM_SMEM>>>(zb, wth + offs1[i], wtl + offs1[i],
                                                 bl1 + i * HH, tb, HH, 1);
        gemm_hmma<<<gemm_grid, 256, GEMM_SMEM>>>(tb, wth + offs2[i], wtl + offs2[i],
                                                 bl2 + i * HH, zb, HH, 1);
        bn_zero_kernel<<<1, 512>>>();
        bn_stats_kernel<<<NN / 256, 256>>>(zb);
        bn_apply_kernel<<<(NN * HH) / 256, 256>>>(zb, gl + i * HH, bel + i * HH, hb);
    }

    // ---- assignment ----
    gemm_hmma<<<gemm_grid, 256, GEMM_SMEM>>>(hb, wth + O_C1, wtl + O_C1, c1b, tb, HH, 2);
    assign_kernel<<<NN / 8, 256>>>(tb, c2w, c2b, ab);

    // ---- pooling / penalty / head ----
    pool_kernel<<<BB, 256>>>(hb, ab, out_sub, out_graph);
    adj_kernel<<<BB, 128>>>(ab, src, dst);
    pen_reduce_kernel<<<1, BB>>>(out_pen);
    head_kernel<<<BB, 256>>>(out_sub, l1w, l1b, l2w, l2b, out_logits);
}